// round 10
// baseline (speedup 1.0000x reference)
#include <cuda_runtime.h>
#include <cuda_bf16.h>

// MultiPrototypeLoss — persistent, BARRIER-FREE block (smem slot ring).
// B=16384, C=1000, P=4; 262MB once-read stream.
// d[b,c] = -logsumexp(-x[b,4c..4c+3]); loss = mean_b (d[b,l]/out_mean)^2.
//
// R9 (dynamic rows, per-row __syncthreads) = 78.6% DRAM: the block runs at
// its slowest warp's pace every row. Here warps FREE-RUN over a 4-slot row
// ring: per row each warp adds its two partials to smem float atomics and
// arrives on a slot counter; the last-arriving warp finalizes the row,
// grabs the next row from the global counter, and republishes the slot.
// No __syncthreads in the loop -> no straggler lockstep.
// Labels: runtime int32/int64 detection (JAX x64 ambiguity).

#define NUM_C   1000
#define THREADS 256
#define WARPS   (THREADS / 32)
#define GRID    (148 * 8)
#define NSLOT   4               // warps may run up to NSLOT-1 rows apart

__device__ double   g_acc   = 0.0;
__device__ unsigned g_count = 0u;
__device__ unsigned g_row   = 0u;    // next unclaimed row

__global__ __launch_bounds__(THREADS, 8) void mpl_kernel(
    const float4* __restrict__ dist,       // [B, NUM_C] float4 groups
    const int*    __restrict__ labels_raw, // [B] int32 OR int64 (as words)
    float*        __restrict__ out,
    int B)
{
    const int tid = threadIdx.x;
    const int lid = tid & 31;

    __shared__ int            s_row[NSLOT];
    __shared__ volatile int   s_seq[NSLOT];   // iteration currently resident
    __shared__ float          s_sum[NSLOT];
    __shared__ float          s_in [NSLOT];
    __shared__ unsigned       s_cnt[NSLOT];

    // --- prologue: one thread seeds the ring with NSLOT rows ---
    if (tid == 0) {
        unsigned base = atomicAdd(&g_row, NSLOT);
#pragma unroll
        for (int k = 0; k < NSLOT; k++) {
            s_row[k] = (int)(base + k);
            s_sum[k] = 0.0f;
            s_in [k] = 0.0f;
            s_cnt[k] = 0u;
            s_seq[k] = k;
        }
    }

    // --- inline label-dtype detection (also orders ring init) ---
    int odd_idx = 2 * tid + 1;
    int nz = (odd_idx < B) ? (labels_raw[odd_idx] != 0) : 0;
    const int labels_are_i32 = __syncthreads_or(nz);

    const int c0 = tid;
    const int c1 = tid + THREADS;
    const int c2 = tid + 2 * THREADS;
    const int c3 = tid + 3 * THREADS;
    const bool has3 = (c3 < NUM_C);          // tid < 232

    double local_acc = 0.0;                  // meaningful on lane 0

    for (int i = 0; ; i++) {
        const int slot = i & (NSLOT - 1);

        // wait until this iteration's row is published (rarely spins)
        while (s_seq[slot] < i) { }
        __threadfence_block();               // acquire: s_row valid
        const int row = s_row[slot];
        if (row >= B) break;                 // same exit point for all warps

        const float4* rowp = dist + (size_t)row * NUM_C;
        const int lbl = labels_are_i32 ? labels_raw[row]
                                       : labels_raw[2 * row];

        float4 v0 = __ldcs(rowp + c0);
        float4 v1 = __ldcs(rowp + c1);
        float4 v2 = __ldcs(rowp + c2);
        float4 v3;
        if (has3) v3 = __ldcs(rowp + c3);

        // per-group softmin pieces; fold logs: Σd = Σm - log(Πs)
        float mm, sp, in_val = 0.0f;
        {
            float m = fminf(fminf(v0.x, v0.y), fminf(v0.z, v0.w));
            float s = (__expf(m - v0.x) + __expf(m - v0.y)) +
                      (__expf(m - v0.z) + __expf(m - v0.w));
            if (c0 == lbl) in_val = m - __logf(s);
            mm = m; sp = s;
        }
        {
            float m = fminf(fminf(v1.x, v1.y), fminf(v1.z, v1.w));
            float s = (__expf(m - v1.x) + __expf(m - v1.y)) +
                      (__expf(m - v1.z) + __expf(m - v1.w));
            if (c1 == lbl) in_val = m - __logf(s);
            mm += m; sp *= s;
        }
        {
            float m = fminf(fminf(v2.x, v2.y), fminf(v2.z, v2.w));
            float s = (__expf(m - v2.x) + __expf(m - v2.y)) +
                      (__expf(m - v2.z) + __expf(m - v2.w));
            if (c2 == lbl) in_val = m - __logf(s);
            mm += m; sp *= s;
        }
        if (has3) {
            float m = fminf(fminf(v3.x, v3.y), fminf(v3.z, v3.w));
            float s = (__expf(m - v3.x) + __expf(m - v3.y)) +
                      (__expf(m - v3.z) + __expf(m - v3.w));
            if (c3 == lbl) in_val = m - __logf(s);
            mm += m; sp *= s;
        }

        float sum_d = mm - __logf(sp);
        // warp reduce both values (in_val nonzero on at most one lane)
#pragma unroll
        for (int off = 16; off > 0; off >>= 1) {
            sum_d  += __shfl_xor_sync(0xFFFFFFFFu, sum_d,  off);
            in_val += __shfl_xor_sync(0xFFFFFFFFu, in_val, off);
        }

        if (lid == 0) {
            atomicAdd(&s_sum[slot], sum_d);
            atomicAdd(&s_in [slot], in_val);
            __threadfence_block();           // partials before arrival
            unsigned old = atomicAdd(&s_cnt[slot], 1u);
            if (old == WARPS - 1) {
                // last warp in: finalize row, recycle slot
                __threadfence_block();
                float tot = s_sum[slot];
                float inc = s_in[slot];
                float out_mean = (tot - inc) * (1.0f / (NUM_C - 1));
                float r = inc / out_mean;
                local_acc += (double)(r * r);

                int nrow = (int)atomicAdd(&g_row, 1u);
                s_row[slot] = nrow;          // may be >= B (exit signal)
                s_sum[slot] = 0.0f;
                s_in [slot] = 0.0f;
                s_cnt[slot] = 0u;
                __threadfence_block();       // release
                s_seq[slot] = i + NSLOT;     // publish
            }
        }
    }

    // per-warp accumulate; warp-count-based finalize
    if (lid == 0) {
        atomicAdd(&g_acc, local_acc);
        __threadfence();
        unsigned t = atomicAdd(&g_count, 1u);
        if (t == (unsigned)(GRID * WARPS) - 1u) {   // last warp overall
            double a = atomicAdd(&g_acc, 0.0);
            *out = (float)(a / (double)B);
            g_acc   = 0.0;                  // restore invariants for replay
            g_count = 0u;
            g_row   = 0u;
        }
    }
}

extern "C" void kernel_launch(void* const* d_in, const int* in_sizes, int n_in,
                              void* d_out, int out_size) {
    const float4* dist   = (const float4*)d_in[0];
    const int*    labels = (const int*)d_in[1];
    float*        out    = (float*)d_out;
    const int B = in_sizes[1];   // label element count == batch size

    mpl_kernel<<<GRID, THREADS>>>(dist, labels, out, B);
}

// round 11
// speedup vs baseline: 1.0679x; 1.0679x over previous
#include <cuda_runtime.h>
#include <cuda_bf16.h>
#include <cstdint>

// MultiPrototypeLoss — persistent kernel, cp.async 3-slot row pipeline.
// B=16384, C=1000, P=4; 262MB once-read stream.
// d[b,c] = -logsumexp(-x[b,4c..4c+3]); loss = mean_b (d[b,l]/out_mean)^2.
//
// Register kernels pin at 74-79% DRAM: avg outstanding bytes (<=4KB/SM,
// ~15% duty) < BW*latency (~13.4KB/SM). cp.async.cg has no register cost
// and no depth cap: keep 2 full rows (32KB/block, 128KB/SM) in flight in a
// 3-slot smem ring. Each thread copies AND consumes its own bytes, so
// cp.async.wait_group is the only data ordering needed. One barrier/row
// (reduce + dynamic row publish), fully covered by the ring.
// Labels: runtime int32/int64 detection (JAX x64 ambiguity).

#define NUM_C     1000
#define THREADS   512
#define WARPS     (THREADS / 32)
#define GRID      (148 * 4)       // 4 blocks/SM (smem-limited), full 2048 thr
#define ROW_BYTES (NUM_C * 16)    // 16000
#define NSLOT     3

__device__ double   g_acc   = 0.0;
__device__ unsigned g_count = 0u;
__device__ unsigned g_row   = 0u;    // next unclaimed row

#define CP16(dst_u32, src) \
    asm volatile("cp.async.cg.shared.global [%0], [%1], 16;" \
                 :: "r"(dst_u32), "l"(src) : "memory")
#define CP_COMMIT() asm volatile("cp.async.commit_group;" ::: "memory")
#define CP_WAIT2()  asm volatile("cp.async.wait_group 2;"  ::: "memory")

__global__ __launch_bounds__(THREADS, 4) void mpl_kernel(
    const char* __restrict__ dist,        // [B] rows of 16000 bytes
    const int*  __restrict__ labels_raw,  // [B] int32 OR int64 (as words)
    float*      __restrict__ out,
    int B)
{
    __shared__ alignas(16) char buf[NSLOT][ROW_BYTES];   // 48000 B
    __shared__ float s_sum[2][WARPS];
    __shared__ float s_in[2];
    __shared__ int   s_base;
    __shared__ int   s_next[2];

    const int tid = threadIdx.x;
    const int lid = tid & 31;
    const int wid = tid >> 5;
    const bool has1 = tid < (NUM_C - THREADS);           // tid < 488

    if (tid == 0) s_base = (int)atomicAdd(&g_row, 3u);

    // --- label dtype detect; its barrier also publishes s_base ---
    int odd = 2 * tid + 1;
    int nz = (odd < B) ? (labels_raw[odd] != 0) : 0;
    const int i32lab = __syncthreads_or(nz);

    const uint32_t smem0 = (uint32_t)__cvta_generic_to_shared(&buf[0][0]);
    const uint32_t off0  = (uint32_t)tid * 16u;
    const uint32_t off1  = off0 + THREADS * 16u;

    int r_cur = s_base, r_n1 = s_base + 1, r_n2 = s_base + 2;

    // ---- prologue: issue rows r_cur (slot0), r_n1 (slot1): 2 groups ----
    if (r_cur < B) {
        const char* g = dist + (size_t)r_cur * ROW_BYTES;
        CP16(smem0 + off0, g + off0);
        if (has1) CP16(smem0 + off1, g + off1);
    }
    CP_COMMIT();
    if (r_n1 < B) {
        const char* g = dist + (size_t)r_n1 * ROW_BYTES;
        CP16(smem0 + ROW_BYTES + off0, g + off0);
        if (has1) CP16(smem0 + ROW_BYTES + off1, g + off1);
    }
    CP_COMMIT();

    double local_acc = 0.0;     // meaningful on tid 0
    int par = 0;
    int sl_iss = 2;             // slot for next issued row
    int sl_con = 0;             // slot holding r_cur

    while (r_cur < B) {
        // ---- issue r_n2 into sl_iss (keeps 2 rows ahead in flight) ----
        if (r_n2 < B) {
            const uint32_t sb = smem0 + (uint32_t)sl_iss * ROW_BYTES;
            const char* g = dist + (size_t)r_n2 * ROW_BYTES;
            CP16(sb + off0, g + off0);
            if (has1) CP16(sb + off1, g + off1);
        }
        CP_COMMIT();            // empty group OK near the tail

        // ---- wait for r_cur's group (leave 2 younger outstanding) ----
        CP_WAIT2();

        const int lbl = i32lab ? labels_raw[r_cur] : labels_raw[2 * r_cur];

        const float4* bp = (const float4*)&buf[sl_con][0];
        float4 v0 = bp[tid];
        float4 v1;
        if (has1) v1 = bp[tid + THREADS];

        // softmin pieces, folded logs: Σd = Σm - log(Πs)
        float mm, sp;
        {
            float m = fminf(fminf(v0.x, v0.y), fminf(v0.z, v0.w));
            float s = (__expf(m - v0.x) + __expf(m - v0.y)) +
                      (__expf(m - v0.z) + __expf(m - v0.w));
            if (tid == lbl) s_in[par] = m - __logf(s);
            mm = m; sp = s;
        }
        if (has1) {
            float m = fminf(fminf(v1.x, v1.y), fminf(v1.z, v1.w));
            float s = (__expf(m - v1.x) + __expf(m - v1.y)) +
                      (__expf(m - v1.z) + __expf(m - v1.w));
            if (tid + THREADS == lbl) s_in[par] = m - __logf(s);
            mm += m; sp *= s;
        }
        float sum_d = mm - __logf(sp);

#pragma unroll
        for (int off = 16; off > 0; off >>= 1)
            sum_d += __shfl_xor_sync(0xFFFFFFFFu, sum_d, off);
        if (lid == 0) s_sum[par][wid] = sum_d;

        // dynamic grab of the row 3 ahead (ATOMG hidden behind the row)
        if (tid == 0) s_next[par] = (int)atomicAdd(&g_row, 1u);

        __syncthreads();        // one barrier per row

        if (tid == 0) {
            float tot = 0.0f;
#pragma unroll
            for (int w = 0; w < WARPS; w++) tot += s_sum[par][w];
            float inc = s_in[par];
            float out_mean = (tot - inc) * (1.0f / (NUM_C - 1));
            float r = inc / out_mean;
            local_acc += (double)(r * r);
        }

        // shift the row window
        r_cur = r_n1; r_n1 = r_n2; r_n2 = s_next[par];
        sl_con = (sl_con == NSLOT - 1) ? 0 : sl_con + 1;
        sl_iss = (sl_iss == NSLOT - 1) ? 0 : sl_iss + 1;
        par ^= 1;
    }

    if (tid == 0) {
        atomicAdd(&g_acc, local_acc);
        __threadfence();
        unsigned t = atomicAdd(&g_count, 1u);
        if (t == gridDim.x - 1) {          // last block: finalize + reset
            double a = atomicAdd(&g_acc, 0.0);
            *out = (float)(a / (double)B);
            g_acc   = 0.0;                 // restore invariants for replay
            g_count = 0u;
            g_row   = 0u;
        }
    }
}

extern "C" void kernel_launch(void* const* d_in, const int* in_sizes, int n_in,
                              void* d_out, int out_size) {
    const char* dist   = (const char*)d_in[0];
    const int*  labels = (const int*)d_in[1];
    float*      out    = (float*)d_out;
    const int B = in_sizes[1];   // label element count == batch size

    mpl_kernel<<<GRID, THREADS>>>(dist, labels, out, B);
}

// round 12
// speedup vs baseline: 1.1559x; 1.0825x over previous
#include <cuda_runtime.h>
#include <cuda_bf16.h>
#include <cstdint>

// MultiPrototypeLoss — persistent, TMA-bulk 3-slot row ring + dynamic rows.
// B=16384, C=1000, P=4; 262MB once-read stream.
// d[b,c] = -logsumexp(-x[b,4c..4c+3]); loss = mean_b (d[b,l]/out_mean)^2.
//
// Register LDG kernels pin at ~78% DRAM (outstanding bytes ~= BW*latency,
// no headroom); cp.async can't exceed 8 B/cyc/SM (LSU floor). cp.async.bulk
// moves a whole 16000B row per INSTRUCTION on the same LTS path: 3-slot
// ring keeps 2 rows/block permanently in flight (~96KB/SM outstanding).
// Slot recycling is ordered by the existing one-barrier-per-row; consumer
// reads LDS.128 (29cyc) instead of LDG (600cyc). Dynamic row scheduling
// (R9 win) retained. Labels: runtime int32/int64 detection.

#define NUM_C     1000
#define THREADS   512
#define WARPS     (THREADS / 32)
#define GRID      (148 * 4)       // 4 blocks/SM (smem-limited)
#define ROW_BYTES (NUM_C * 16)    // 16000
#define NSLOT     3

__device__ double   g_acc   = 0.0;
__device__ unsigned g_count = 0u;
__device__ unsigned g_row   = 0u;    // next unclaimed row

__device__ __forceinline__ uint32_t smem_u32(const void* p) {
    return (uint32_t)__cvta_generic_to_shared(p);
}
__device__ __forceinline__ void mbar_init(uint32_t mbar, uint32_t cnt) {
    asm volatile("mbarrier.init.shared.b64 [%0], %1;" :: "r"(mbar), "r"(cnt) : "memory");
}
__device__ __forceinline__ void mbar_expect_tx(uint32_t mbar, uint32_t bytes) {
    asm volatile("mbarrier.arrive.expect_tx.shared.b64 _, [%0], %1;"
                 :: "r"(mbar), "r"(bytes) : "memory");
}
__device__ __forceinline__ void mbar_wait(uint32_t mbar, uint32_t parity) {
    asm volatile(
        "{\n\t.reg .pred P;\n\t"
        "WL%=:\n\t"
        "mbarrier.try_wait.parity.acquire.cta.shared::cta.b64 P, [%0], %1, 0x989680;\n\t"
        "@P bra WD%=;\n\t"
        "bra WL%=;\n\t"
        "WD%=:\n\t}"
        :: "r"(mbar), "r"(parity) : "memory");
}
__device__ __forceinline__ void bulk_copy(uint32_t dst_smem, const void* src,
                                          uint32_t bytes, uint32_t mbar) {
    asm volatile(
        "cp.async.bulk.shared::cta.global.mbarrier::complete_tx::bytes [%0], [%1], %2, [%3];"
        :: "r"(dst_smem), "l"(src), "r"(bytes), "r"(mbar) : "memory");
}

__global__ __launch_bounds__(THREADS, 4) void mpl_kernel(
    const char* __restrict__ dist,        // [B] rows of 16000 bytes
    const int*  __restrict__ labels_raw,  // [B] int32 OR int64 (as words)
    float*      __restrict__ out,
    int B)
{
    __shared__ alignas(16) char buf[NSLOT][ROW_BYTES];   // 48000 B
    __shared__ unsigned long long mbar_s[NSLOT];
    __shared__ float s_sum[2][WARPS];
    __shared__ float s_in[2];
    __shared__ int   s_next[2];
    __shared__ int   s_base;

    const int tid = threadIdx.x;
    const int lid = tid & 31;
    const int wid = tid >> 5;
    const bool has1 = tid < (NUM_C - THREADS);           // tid < 488

    if (tid == 0) {
        s_base = (int)atomicAdd(&g_row, (unsigned)NSLOT);
#pragma unroll
        for (int s = 0; s < NSLOT; s++) mbar_init(smem_u32(&mbar_s[s]), 1);
    }

    // --- label dtype detect; barrier also publishes s_base + mbar init ---
    int odd = 2 * tid + 1;
    int nz = (odd < B) ? (labels_raw[odd] != 0) : 0;
    const int i32lab = __syncthreads_or(nz);

    int r_cur = s_base, r_n1 = s_base + 1, r_n2 = s_base + 2;

    // ---- prologue: issue rows r_cur -> slot0, r_n1 -> slot1 ----
    if (tid == 0) {
        if (r_cur < B) {
            uint32_t m = smem_u32(&mbar_s[0]);
            mbar_expect_tx(m, ROW_BYTES);
            bulk_copy(smem_u32(&buf[0][0]), dist + (size_t)r_cur * ROW_BYTES,
                      ROW_BYTES, m);
        }
        if (r_n1 < B) {
            uint32_t m = smem_u32(&mbar_s[1]);
            mbar_expect_tx(m, ROW_BYTES);
            bulk_copy(smem_u32(&buf[1][0]), dist + (size_t)r_n1 * ROW_BYTES,
                      ROW_BYTES, m);
        }
    }

    double local_acc = 0.0;     // meaningful on tid 0
    int par  = 0;
    int slot = 0;               // slot holding r_cur
    int ph   = 0;               // parity for current slot's use

    while (r_cur < B) {
        // ---- issue r_n2 into slot+2 (drained at barrier of prev iter) ----
        if (tid == 0 && r_n2 < B) {
            int si = slot + 2; if (si >= NSLOT) si -= NSLOT;
            uint32_t m = smem_u32(&mbar_s[si]);
            mbar_expect_tx(m, ROW_BYTES);
            bulk_copy(smem_u32(&buf[si][0]), dist + (size_t)r_n2 * ROW_BYTES,
                      ROW_BYTES, m);
        }

        // ---- wait for r_cur's row ----
        mbar_wait(smem_u32(&mbar_s[slot]), (uint32_t)ph);

        const int lbl = i32lab ? labels_raw[r_cur] : labels_raw[2 * r_cur];

        const float4* bp = (const float4*)&buf[slot][0];
        float4 v0 = bp[tid];
        float4 v1;
        if (has1) v1 = bp[tid + THREADS];

        // softmin pieces, folded logs: Σd = Σm - log(Πs)
        float mm, sp;
        {
            float m = fminf(fminf(v0.x, v0.y), fminf(v0.z, v0.w));
            float s = (__expf(m - v0.x) + __expf(m - v0.y)) +
                      (__expf(m - v0.z) + __expf(m - v0.w));
            if (tid == lbl) s_in[par] = m - __logf(s);
            mm = m; sp = s;
        }
        if (has1) {
            float m = fminf(fminf(v1.x, v1.y), fminf(v1.z, v1.w));
            float s = (__expf(m - v1.x) + __expf(m - v1.y)) +
                      (__expf(m - v1.z) + __expf(m - v1.w));
            if (tid + THREADS == lbl) s_in[par] = m - __logf(s);
            mm += m; sp *= s;
        }
        float sum_d = mm - __logf(sp);

#pragma unroll
        for (int off = 16; off > 0; off >>= 1)
            sum_d += __shfl_xor_sync(0xFFFFFFFFu, sum_d, off);
        if (lid == 0) s_sum[par][wid] = sum_d;

        // dynamic grab of the row 3 ahead (ATOMG hidden behind the row)
        if (tid == 0) s_next[par] = (int)atomicAdd(&g_row, 1u);

        __syncthreads();        // one barrier/row: reduce + slot drain + grab

        if (tid == 0) {
            float tot = 0.0f;
#pragma unroll
            for (int w = 0; w < WARPS; w++) tot += s_sum[par][w];
            float inc = s_in[par];
            float out_mean = (tot - inc) * (1.0f / (NUM_C - 1));
            float r = inc / out_mean;
            local_acc += (double)(r * r);
        }

        // advance window
        r_cur = r_n1; r_n1 = r_n2; r_n2 = s_next[par];
        par ^= 1;
        slot++; if (slot == NSLOT) { slot = 0; ph ^= 1; }
    }

    if (tid == 0) {
        atomicAdd(&g_acc, local_acc);
        __threadfence();
        unsigned t = atomicAdd(&g_count, 1u);
        if (t == gridDim.x - 1) {          // last block: finalize + reset
            double a = atomicAdd(&g_acc, 0.0);
            *out = (float)(a / (double)B);
            g_acc   = 0.0;                 // restore invariants for replay
            g_count = 0u;
            g_row   = 0u;
        }
    }
}

extern "C" void kernel_launch(void* const* d_in, const int* in_sizes, int n_in,
                              void* d_out, int out_size) {
    const char* dist   = (const char*)d_in[0];
    const int*  labels = (const int*)d_in[1];
    float*      out    = (float*)d_out;
    const int B = in_sizes[1];   // label element count == batch size

    mpl_kernel<<<GRID, THREADS>>>(dist, labels, out, B);
}

// round 13
// speedup vs baseline: 1.2833x; 1.1102x over previous
#include <cuda_runtime.h>
#include <cuda_bf16.h>

// MultiPrototypeLoss — persistent block-per-row, dynamic rows (R9 frame)
// + base-2 math + per-group compute/prefetch interleave.
// B=16384, C=1000, P=4; 262MB once-read stream (HBM-bound).
// d[b,c] = -logsumexp(-x[b,4c..4c+3]); loss = mean_b (d[b,l]/out_mean)^2.
//
// Base-2: u_i = fma(v_i, -log2e, m*log2e); s = sum exp2(u_i) in [1,4];
//         sum_d = sum m - ln2 * log2(prod s)  (prod s in [1,256], exact-safe).
// Next-row LDGs issue per-group as each v register dies, starting the
// prefetch ~200 cycles earlier than the R9 bulk prefetch.
// Labels: runtime int32/int64 detection (JAX x64 ambiguity).

#define NUM_C   1000
#define THREADS 256
#define WARPS   (THREADS / 32)
#define GRID    (148 * 8)

#define L2E  1.4426950408889634f   // log2(e)
#define LN2  0.6931471805599453f

__device__ double   g_acc   = 0.0;
__device__ unsigned g_count = 0u;
__device__ unsigned g_row   = GRID;   // next unclaimed row

__device__ __forceinline__ void group_ms(float4 v, float& m, float& s) {
    m = fminf(fminf(v.x, v.y), fminf(v.z, v.w));
    float mL = m * L2E;
    s = (exp2f(fmaf(v.x, -L2E, mL)) + exp2f(fmaf(v.y, -L2E, mL))) +
        (exp2f(fmaf(v.z, -L2E, mL)) + exp2f(fmaf(v.w, -L2E, mL)));
}

__global__ __launch_bounds__(THREADS, 8) void mpl_kernel(
    const float4* __restrict__ dist,       // [B, NUM_C] float4 groups
    const int*    __restrict__ labels_raw, // [B] int32 OR int64 (as words)
    float*        __restrict__ out,
    int B)
{
    const int tid = threadIdx.x;
    const int lid = tid & 31;
    const int wid = tid >> 5;

    __shared__ int   s_next[2];
    __shared__ float s_sum[2][WARPS];
    __shared__ float s_in_m[2];
    __shared__ float s_in_s[2];

    if (tid == 0) s_next[0] = (int)atomicAdd(&g_row, 1u);

    // --- inline label-dtype detection; barrier publishes s_next[0] too ---
    int odd_idx = 2 * tid + 1;
    int nz = (odd_idx < B) ? (labels_raw[odd_idx] != 0) : 0;
    const int labels_are_i32 = __syncthreads_or(nz);

    const int c0 = tid;
    const int c1 = tid + THREADS;
    const int c2 = tid + 2 * THREADS;
    const int c3 = tid + 3 * THREADS;
    const bool has3 = (c3 < NUM_C);          // tid < 232

    double local_acc = 0.0;                  // meaningful on tid 0
    int par = 0;

    int row  = blockIdx.x;                   // r_i
    int rown = s_next[0];                    // r_{i+1}

    float4 v0, v1, v2, v3;
    int lbl = 0;
    if (row < B) {
        const float4* rowp = dist + (size_t)row * NUM_C;
        lbl = labels_are_i32 ? labels_raw[row] : labels_raw[2 * row];
        v0 = __ldcs(rowp + c0);
        v1 = __ldcs(rowp + c1);
        v2 = __ldcs(rowp + c2);
        if (has3) v3 = __ldcs(rowp + c3);
    }

    while (row < B) {
        const int cur_lbl = lbl;
        const bool  pf    = (rown < B);
        const float4* nrowp = dist + (size_t)rown * NUM_C;
        if (pf) lbl = labels_are_i32 ? labels_raw[rown] : labels_raw[2 * rown];

        // grab r_{i+2} early (ATOMG latency hidden behind the whole row)
        if (tid == 0) s_next[par ^ 1] = (int)atomicAdd(&g_row, 1u);

        // ---- per-group compute; reload each v as it dies ----
        float mm, sp;
        {
            float m, s; group_ms(v0, m, s);
            if (pf) v0 = __ldcs(nrowp + c0);
            if (c0 == cur_lbl) { s_in_m[par] = m; s_in_s[par] = s; }
            mm = m; sp = s;
        }
        {
            float m, s; group_ms(v1, m, s);
            if (pf) v1 = __ldcs(nrowp + c1);
            if (c1 == cur_lbl) { s_in_m[par] = m; s_in_s[par] = s; }
            mm += m; sp *= s;
        }
        {
            float m, s; group_ms(v2, m, s);
            if (pf) v2 = __ldcs(nrowp + c2);
            if (c2 == cur_lbl) { s_in_m[par] = m; s_in_s[par] = s; }
            mm += m; sp *= s;
        }
        if (has3) {
            float m, s; group_ms(v3, m, s);
            if (pf) v3 = __ldcs(nrowp + c3);
            if (c3 == cur_lbl) { s_in_m[par] = m; s_in_s[par] = s; }
            mm += m; sp *= s;
        }

        // ---- epilogue: fold logs, reduce, one barrier ----
        float sum_d = fmaf(-LN2, __log2f(sp), mm);
#pragma unroll
        for (int off = 16; off > 0; off >>= 1)
            sum_d += __shfl_xor_sync(0xFFFFFFFFu, sum_d, off);
        if (lid == 0) s_sum[par][wid] = sum_d;

        __syncthreads();   // single barrier per row (parity protects reuse)

        if (tid == 0) {
            float tot = 0.0f;
#pragma unroll
            for (int w = 0; w < WARPS; w++) tot += s_sum[par][w];
            float inc = fmaf(-LN2, __log2f(s_in_s[par]), s_in_m[par]);
            float out_mean = (tot - inc) * (1.0f / (NUM_C - 1));
            float r = inc / out_mean;
            local_acc += (double)(r * r);
        }

        row  = rown;
        rown = s_next[par ^ 1];   // r_{i+2}, visible post-barrier
        par ^= 1;
    }

    if (tid == 0) {
        atomicAdd(&g_acc, local_acc);
        __threadfence();
        unsigned t = atomicAdd(&g_count, 1u);
        if (t == gridDim.x - 1) {          // last block: finalize + reset
            double a = atomicAdd(&g_acc, 0.0);
            *out = (float)(a / (double)B);
            g_acc   = 0.0;                 // restore invariants for replay
            g_count = 0u;
            g_row   = GRID;
        }
    }
}

extern "C" void kernel_launch(void* const* d_in, const int* in_sizes, int n_in,
                              void* d_out, int out_size) {
    const float4* dist   = (const float4*)d_in[0];
    const int*    labels = (const int*)d_in[1];
    float*        out    = (float*)d_out;
    const int B = in_sizes[1];   // label element count == batch size

    mpl_kernel<<<GRID, THREADS>>>(dist, labels, out, B);
}

// round 14
// speedup vs baseline: 1.3124x; 1.0227x over previous
#include <cuda_runtime.h>
#include <cuda_bf16.h>

// MultiPrototypeLoss — persistent block-per-row, dynamic rows (R9 frame,
// unchanged load schedule) + base-2 softmin math.
// B=16384, C=1000, P=4; 262MB once-read stream (HBM-bound).
// d[b,c] = -logsumexp(-x[b,4c..4c+3]); loss = mean_b (d[b,l]/out_mean)^2.
//
// R9: batched 4x LDG.128 prefetch AFTER the softmin block (keeps the
// consecutive-front MLP shape that R13's interleave destroyed).
// Base-2: u_i = fma(v_i, -log2e, m*log2e); s = sum exp2(u_i) in [1,4];
//         sum_d = sum m - ln2*log2(prod s), prod s in [1,256] (safe).
// Labels: runtime int32/int64 detection (JAX x64 ambiguity).

#define NUM_C   1000
#define THREADS 256
#define WARPS   (THREADS / 32)
#define GRID    (148 * 8)

#define L2E  1.4426950408889634f   // log2(e)
#define LN2  0.6931471805599453f

__device__ double   g_acc   = 0.0;
__device__ unsigned g_count = 0u;
__device__ unsigned g_row   = GRID;   // next unclaimed row

__device__ __forceinline__ void group_ms(float4 v, float& m, float& s) {
    m = fminf(fminf(v.x, v.y), fminf(v.z, v.w));
    float mL = m * L2E;
    s = (exp2f(fmaf(v.x, -L2E, mL)) + exp2f(fmaf(v.y, -L2E, mL))) +
        (exp2f(fmaf(v.z, -L2E, mL)) + exp2f(fmaf(v.w, -L2E, mL)));
}

__global__ __launch_bounds__(THREADS, 8) void mpl_kernel(
    const float4* __restrict__ dist,       // [B, NUM_C] float4 groups
    const int*    __restrict__ labels_raw, // [B] int32 OR int64 (as words)
    float*        __restrict__ out,
    int B)
{
    const int tid = threadIdx.x;
    const int lid = tid & 31;
    const int wid = tid >> 5;

    __shared__ int   s_next[2];
    __shared__ float s_sum[2][WARPS];
    __shared__ float s_in_m[2];
    __shared__ float s_in_s[2];

    // prologue grab of r1 (r0 = blockIdx.x is static)
    if (tid == 0) s_next[0] = (int)atomicAdd(&g_row, 1u);

    // --- inline label-dtype detection; barrier publishes s_next[0] too ---
    int odd_idx = 2 * tid + 1;
    int nz = (odd_idx < B) ? (labels_raw[odd_idx] != 0) : 0;
    const int labels_are_i32 = __syncthreads_or(nz);

    const int c0 = tid;
    const int c1 = tid + THREADS;
    const int c2 = tid + 2 * THREADS;
    const int c3 = tid + 3 * THREADS;
    const bool has3 = (c3 < NUM_C);          // tid < 232

    double local_acc = 0.0;                  // meaningful on tid 0
    int par = 0;

    int row  = blockIdx.x;                   // r_i
    int rown = s_next[0];                    // r_{i+1}

    // ---- prologue: load first row ----
    float4 v0, v1, v2, v3;
    int lbl = 0;
    if (row < B) {
        const float4* rowp = dist + (size_t)row * NUM_C;
        lbl = labels_are_i32 ? labels_raw[row] : labels_raw[2 * row];
        v0 = __ldcs(rowp + c0);
        v1 = __ldcs(rowp + c1);
        v2 = __ldcs(rowp + c2);
        if (has3) v3 = __ldcs(rowp + c3);
    }

    while (row < B) {
        const int cur_lbl = lbl;

        // ---- per-group softmin pieces (base-2, folded logs) ----
        float mm, sp;
        {
            float m, s; group_ms(v0, m, s);
            if (c0 == cur_lbl) { s_in_m[par] = m; s_in_s[par] = s; }
            mm = m; sp = s;
        }
        {
            float m, s; group_ms(v1, m, s);
            if (c1 == cur_lbl) { s_in_m[par] = m; s_in_s[par] = s; }
            mm += m; sp *= s;
        }
        {
            float m, s; group_ms(v2, m, s);
            if (c2 == cur_lbl) { s_in_m[par] = m; s_in_s[par] = s; }
            mm += m; sp *= s;
        }
        if (has3) {
            float m, s; group_ms(v3, m, s);
            if (c3 == cur_lbl) { s_in_m[par] = m; s_in_s[par] = s; }
            mm += m; sp *= s;
        }

        // ---- batched prefetch of r_{i+1} into freed v regs (pre-barrier) ----
        if (rown < B) {
            const float4* nrowp = dist + (size_t)rown * NUM_C;
            lbl = labels_are_i32 ? labels_raw[rown] : labels_raw[2 * rown];
            v0 = __ldcs(nrowp + c0);
            v1 = __ldcs(nrowp + c1);
            v2 = __ldcs(nrowp + c2);
            if (has3) v3 = __ldcs(nrowp + c3);
        }

        // ---- grab r_{i+2} (latency hidden; consumed after next barrier) ----
        if (tid == 0) s_next[par ^ 1] = (int)atomicAdd(&g_row, 1u);

        // ---- epilogue for current row ----
        float sum_d = fmaf(-LN2, __log2f(sp), mm);
#pragma unroll
        for (int off = 16; off > 0; off >>= 1)
            sum_d += __shfl_xor_sync(0xFFFFFFFFu, sum_d, off);
        if (lid == 0) s_sum[par][wid] = sum_d;

        __syncthreads();   // single barrier per row (parity protects reuse)

        if (tid == 0) {
            float tot = 0.0f;
#pragma unroll
            for (int w = 0; w < WARPS; w++) tot += s_sum[par][w];
            float inc = fmaf(-LN2, __log2f(s_in_s[par]), s_in_m[par]);
            float out_mean = (tot - inc) * (1.0f / (NUM_C - 1));
            float r = inc / out_mean;
            local_acc += (double)(r * r);
        }

        row  = rown;
        rown = s_next[par ^ 1];   // r_{i+2}, visible post-barrier
        par ^= 1;
    }

    if (tid == 0) {
        atomicAdd(&g_acc, local_acc);
        __threadfence();
        unsigned t = atomicAdd(&g_count, 1u);
        if (t == gridDim.x - 1) {          // last block: finalize + reset
            double a = atomicAdd(&g_acc, 0.0);
            *out = (float)(a / (double)B);
            g_acc   = 0.0;                 // restore invariants for replay
            g_count = 0u;
            g_row   = GRID;
        }
    }
}

extern "C" void kernel_launch(void* const* d_in, const int* in_sizes, int n_in,
                              void* d_out, int out_size) {
    const float4* dist   = (const float4*)d_in[0];
    const int*    labels = (const int*)d_in[1];
    float*        out    = (float*)d_out;
    const int B = in_sizes[1];   // label element count == batch size

    mpl_kernel<<<GRID, THREADS>>>(dist, labels, out, B);
}

// round 15
// speedup vs baseline: 1.3950x; 1.0630x over previous
#include <cuda_runtime.h>
#include <cuda_bf16.h>

// MultiPrototypeLoss — persistent block-per-row, dynamic rows (R9 frame)
// + base-2 softmin + BULK L2 PREFETCH of row i+2.
// B=16384, C=1000, P=4; 262MB once-read stream (HBM-bound).
// d[b,c] = -logsumexp(-x[b,4c..4c+3]); loss = mean_b (d[b,l]/out_mean)^2.
//
// All register/smem paths cap at ~78% DRAM: avg outstanding bytes sit
// exactly at BW*latency. cp.async.bulk.prefetch.L2.global moves a whole
// 16000B row DRAM->L2 in ONE instruction (no regs/smem/mbarrier), issued
// ~1.5 rows ahead; the consuming LDG.128s then hit L2 (~240cyc vs ~600),
// cutting the latency the register prefetch must hide by ~2.5x.
// Labels: runtime int32/int64 detection (JAX x64 ambiguity).

#define NUM_C     1000
#define ROW_BYTES (NUM_C * 16)
#define THREADS   256
#define WARPS     (THREADS / 32)
#define GRID      (148 * 8)

#define L2E  1.4426950408889634f   // log2(e)
#define LN2  0.6931471805599453f

__device__ double   g_acc   = 0.0;
__device__ unsigned g_count = 0u;
__device__ unsigned g_row   = GRID;   // next unclaimed row

__device__ __forceinline__ void l2_prefetch_row(const char* p) {
    asm volatile("cp.async.bulk.prefetch.L2.global [%0], %1;"
                 :: "l"(p), "r"(ROW_BYTES) : "memory");
}

__device__ __forceinline__ void group_ms(float4 v, float& m, float& s) {
    m = fminf(fminf(v.x, v.y), fminf(v.z, v.w));
    float mL = m * L2E;
    s = (exp2f(fmaf(v.x, -L2E, mL)) + exp2f(fmaf(v.y, -L2E, mL))) +
        (exp2f(fmaf(v.z, -L2E, mL)) + exp2f(fmaf(v.w, -L2E, mL)));
}

__global__ __launch_bounds__(THREADS, 8) void mpl_kernel(
    const float4* __restrict__ dist,       // [B, NUM_C] float4 groups
    const int*    __restrict__ labels_raw, // [B] int32 OR int64 (as words)
    float*        __restrict__ out,
    int B)
{
    const int tid = threadIdx.x;
    const int lid = tid & 31;
    const int wid = tid >> 5;

    __shared__ int   s_next[2];
    __shared__ float s_sum[2][WARPS];
    __shared__ float s_in_m[2];
    __shared__ float s_in_s[2];

    // prologue grab of r1 (r0 = blockIdx.x is static)
    if (tid == 0) s_next[0] = (int)atomicAdd(&g_row, 1u);

    // --- inline label-dtype detection; barrier publishes s_next[0] too ---
    int odd_idx = 2 * tid + 1;
    int nz = (odd_idx < B) ? (labels_raw[odd_idx] != 0) : 0;
    const int labels_are_i32 = __syncthreads_or(nz);

    const int c0 = tid;
    const int c1 = tid + THREADS;
    const int c2 = tid + 2 * THREADS;
    const int c3 = tid + 3 * THREADS;
    const bool has3 = (c3 < NUM_C);          // tid < 232

    double local_acc = 0.0;                  // meaningful on tid 0
    int par = 0;

    int row  = blockIdx.x;                   // r_i
    int rown = s_next[0];                    // r_{i+1}

    // ---- prologue: load first row; L2-prefetch r_{i+1} ----
    float4 v0, v1, v2, v3;
    int lbl = 0;
    if (tid == 0 && rown < B)
        l2_prefetch_row((const char*)dist + (size_t)rown * ROW_BYTES);
    if (row < B) {
        const float4* rowp = dist + (size_t)row * NUM_C;
        lbl = labels_are_i32 ? labels_raw[row] : labels_raw[2 * row];
        v0 = __ldcs(rowp + c0);
        v1 = __ldcs(rowp + c1);
        v2 = __ldcs(rowp + c2);
        if (has3) v3 = __ldcs(rowp + c3);
    }

    while (row < B) {
        const int cur_lbl = lbl;

        // ---- per-group softmin pieces (base-2, folded logs) ----
        float mm, sp;
        {
            float m, s; group_ms(v0, m, s);
            if (c0 == cur_lbl) { s_in_m[par] = m; s_in_s[par] = s; }
            mm = m; sp = s;
        }
        {
            float m, s; group_ms(v1, m, s);
            if (c1 == cur_lbl) { s_in_m[par] = m; s_in_s[par] = s; }
            mm += m; sp *= s;
        }
        {
            float m, s; group_ms(v2, m, s);
            if (c2 == cur_lbl) { s_in_m[par] = m; s_in_s[par] = s; }
            mm += m; sp *= s;
        }
        if (has3) {
            float m, s; group_ms(v3, m, s);
            if (c3 == cur_lbl) { s_in_m[par] = m; s_in_s[par] = s; }
            mm += m; sp *= s;
        }

        // ---- batched prefetch of r_{i+1} into freed v regs (pre-barrier) ----
        if (rown < B) {
            const float4* nrowp = dist + (size_t)rown * NUM_C;
            lbl = labels_are_i32 ? labels_raw[rown] : labels_raw[2 * rown];
            v0 = __ldcs(nrowp + c0);
            v1 = __ldcs(nrowp + c1);
            v2 = __ldcs(nrowp + c2);
            if (has3) v3 = __ldcs(nrowp + c3);
        }

        // ---- grab r_{i+2} (latency hidden; consumed after next barrier) ----
        if (tid == 0) s_next[par ^ 1] = (int)atomicAdd(&g_row, 1u);

        // ---- epilogue for current row ----
        float sum_d = fmaf(-LN2, __log2f(sp), mm);
#pragma unroll
        for (int off = 16; off > 0; off >>= 1)
            sum_d += __shfl_xor_sync(0xFFFFFFFFu, sum_d, off);
        if (lid == 0) s_sum[par][wid] = sum_d;

        __syncthreads();   // single barrier per row (parity protects reuse)

        if (tid == 0) {
            // L2-prefetch r_{i+2} (just published) ~1.5 rows ahead of its LDGs
            int nr = s_next[par ^ 1];
            if (nr < B)
                l2_prefetch_row((const char*)dist + (size_t)nr * ROW_BYTES);

            float tot = 0.0f;
#pragma unroll
            for (int w = 0; w < WARPS; w++) tot += s_sum[par][w];
            float inc = fmaf(-LN2, __log2f(s_in_s[par]), s_in_m[par]);
            float out_mean = (tot - inc) * (1.0f / (NUM_C - 1));
            float r = inc / out_mean;
            local_acc += (double)(r * r);
        }

        row  = rown;
        rown = s_next[par ^ 1];   // r_{i+2}, visible post-barrier
        par ^= 1;
    }

    if (tid == 0) {
        atomicAdd(&g_acc, local_acc);
        __threadfence();
        unsigned t = atomicAdd(&g_count, 1u);
        if (t == gridDim.x - 1) {          // last block: finalize + reset
            double a = atomicAdd(&g_acc, 0.0);
            *out = (float)(a / (double)B);
            g_acc   = 0.0;                 // restore invariants for replay
            g_count = 0u;
            g_row   = GRID;
        }
    }
}

extern "C" void kernel_launch(void* const* d_in, const int* in_sizes, int n_in,
                              void* d_out, int out_size) {
    const float4* dist   = (const float4*)d_in[0];
    const int*    labels = (const int*)d_in[1];
    float*        out    = (float*)d_out;
    const int B = in_sizes[1];   // label element count == batch size

    mpl_kernel<<<GRID, THREADS>>>(dist, labels, out, B);
}